// round 17
// baseline (speedup 1.0000x reference)
#include <cuda_runtime.h>

// Problem constants (LatentCoulombLongRange: N=8192, F=128, H=64, B=8)
#define MAXN 8192
#define FDIM 128
#define HDIM 64
#define MAXB 64
#define NSLOT 32          // charge-sum slots per graph

#define XS_RS 132         // x tile row stride (words): (4g+c) mod 32 distinct
#define WH_RS 68          // W hi/lo row stride (uint2): per-16-lane phases conflict-free
#define SA_RS 66          // sacc row stride

// Scratch (allocation-free rule: __device__ globals; zero-initialized at load)
__device__ float  d_qraw[MAXN];
__device__ float4 d_qpos[MAXN];            // {x, y, z, centered q}
__device__ int    d_gstart[MAXB];
__device__ int    d_gend[MAXB];
__device__ float  d_gsum[MAXB * NSLOT];    // slotted sums; re-zeroed by pair_kernel

// ---- raw single-MUFU intrinsics ----
__device__ __forceinline__ float fast_rsqrt(float x) {
    float r; asm("rsqrt.approx.ftz.f32 %0, %1;" : "=f"(r) : "f"(x)); return r;
}
__device__ __forceinline__ float fast_ex2(float x) {
    float r; asm("ex2.approx.ftz.f32 %0, %1;" : "=f"(r) : "f"(x)); return r;
}
__device__ __forceinline__ float fast_rcp(float x) {
    float r; asm("rcp.approx.ftz.f32 %0, %1;" : "=f"(r) : "f"(x)); return r;
}
#define LOG2E 1.44269504088896f
__device__ __forceinline__ float silu_f(float v) {
    return v * fast_rcp(1.0f + fast_ex2(-LOG2E * v));
}

// tf32 helpers
__device__ __forceinline__ unsigned int to_tf32(float f) {
    unsigned int u; asm("cvt.rna.tf32.f32 %0, %1;" : "=r"(u) : "f"(f)); return u;
}
__device__ __forceinline__ void mma_tf32(float* d,
                                         unsigned int a0, unsigned int a1,
                                         unsigned int a2, unsigned int a3,
                                         unsigned int b0, unsigned int b1) {
    asm volatile(
        "mma.sync.aligned.m16n8k8.row.col.f32.tf32.tf32.f32 "
        "{%0,%1,%2,%3}, {%4,%5,%6,%7}, {%8,%9}, {%0,%1,%2,%3};"
        : "+f"(d[0]), "+f"(d[1]), "+f"(d[2]), "+f"(d[3])
        : "r"(a0), "r"(a1), "r"(a2), "r"(a3), "r"(b0), "r"(b1));
}

// ---------------------------------------------------------------------------
// K1: charge-head MLP via tf32 tensor cores, v2.
//     Tile = 32 atoms x 64 H, grid = 256 (all SMs busy). W1 hi/lo split is
//     PRECOMPUTED at staging into packed uint2 SMEM (kills the in-loop B
//     conversions that were 14% ALU). K=128 split across warp pairs:
//     warp w -> (kg = w&1, grp = (w>>1)&1, hh = w>>2); partial C tiles
//     combined via SMEM atomics (xs reused as sacc), THEN SiLU + W2 dot.
// ---------------------------------------------------------------------------
__global__ __launch_bounds__(256)
void mlp_kernel(const float* __restrict__ x,
                const float* __restrict__ W1,
                const float* __restrict__ b1,
                const float* __restrict__ W2,
                const float* __restrict__ b2,
                const int* __restrict__ batch,
                int n) {
    __shared__ float xs[32 * XS_RS];   // 16.9 KB; reused as sacc after MMA
    __shared__ uint2 wh2[FDIM * WH_RS];// 69.6 KB: W1 {hi, lo} tf32 pairs

    int t    = threadIdx.x;
    int base = blockIdx.x * 32;

    // stage x tile: 32 atoms x 32 float4 = 1024 f4, 4 per thread
    {
        const float4* xv4 = (const float4*)x;
#pragma unroll
        for (int it = 0; it < 4; it++) {
            int idx = t + it * 256;            // 0..1023
            int row = idx >> 5, c4 = idx & 31;
            int arow = min(base + row, n - 1);
            *(float4*)&xs[row * XS_RS + c4 * 4] = xv4[arow * 32 + c4];
        }
    }
    // stage W1 as {hi, lo} tf32: 128 rows x 16 f4 = 2048 f4, 8 per thread
    {
        const float4* w1v4 = (const float4*)W1;
#pragma unroll
        for (int it = 0; it < 8; it++) {
            int idx = t + it * 256;
            int row = idx >> 4, c4 = idx & 15;
            float4 v = w1v4[row * 16 + c4];
            float vv[4] = {v.x, v.y, v.z, v.w};
#pragma unroll
            for (int j = 0; j < 4; j++) {
                unsigned int hi = to_tf32(vv[j]);
                unsigned int lo = to_tf32(vv[j] - __uint_as_float(hi));
                wh2[row * WH_RS + c4 * 4 + j] = make_uint2(hi, lo);
            }
        }
    }
    __syncthreads();

    int w    = t >> 5;
    int lane = t & 31;
    int g    = lane >> 2;          // 0..7
    int c    = lane & 3;           // 0..3
    int kg   = w & 1;              // K half
    int grp  = (w >> 1) & 1;       // atom group
    int hh   = w >> 2;             // H half
    int m_base = 16 * grp;
    int n_base = 32 * hh;
    int k_base = 64 * kg;

    float d[4][4] = {{0,0,0,0},{0,0,0,0},{0,0,0,0},{0,0,0,0}};

    const float* xsp = xs  + (m_base + g) * XS_RS + k_base + c;
    const uint2* whp = wh2 + c * WH_RS + n_base + g;

#pragma unroll
    for (int kk = 0; kk < 8; kk++) {
        int xo = kk * 8;
        float a0f = xsp[xo];
        float a1f = xsp[8 * XS_RS + xo];
        float a2f = xsp[xo + 4];
        float a3f = xsp[8 * XS_RS + xo + 4];
        unsigned int ah0 = to_tf32(a0f), ah1 = to_tf32(a1f),
                     ah2 = to_tf32(a2f), ah3 = to_tf32(a3f);
        unsigned int al0 = to_tf32(a0f - __uint_as_float(ah0));
        unsigned int al1 = to_tf32(a1f - __uint_as_float(ah1));
        unsigned int al2 = to_tf32(a2f - __uint_as_float(ah2));
        unsigned int al3 = to_tf32(a3f - __uint_as_float(ah3));

        int wo = (k_base + kk * 8) * WH_RS;
#pragma unroll
        for (int nt = 0; nt < 4; nt++) {
            uint2 b0 = whp[wo + nt * 8];
            uint2 b1v = whp[wo + 4 * WH_RS + nt * 8];
            mma_tf32(d[nt], ah0, ah1, ah2, ah3, b0.x, b1v.x);  // hi*hi
            mma_tf32(d[nt], ah0, ah1, ah2, ah3, b0.y, b1v.y);  // hi*lo
            mma_tf32(d[nt], al0, al1, al2, al3, b0.x, b1v.x);  // lo*hi
        }
    }
    __syncthreads();               // all warps done reading xs

    // combine K-half partials: reuse xs as sacc[32][SA_RS]
    float* sacc = xs;
#pragma unroll
    for (int it = 0; it < 9; it++) {
        int idx = t + it * 256;
        if (idx < 32 * SA_RS) sacc[idx] = 0.0f;
    }
    __syncthreads();

#pragma unroll
    for (int nt = 0; nt < 4; nt++) {
        int col = n_base + nt * 8 + 2 * c;
        int row = m_base + g;
        atomicAdd(&sacc[row * SA_RS + col],           d[nt][0]);
        atomicAdd(&sacc[row * SA_RS + col + 1],       d[nt][1]);
        atomicAdd(&sacc[(row + 8) * SA_RS + col],     d[nt][2]);
        atomicAdd(&sacc[(row + 8) * SA_RS + col + 1], d[nt][3]);
    }
    __syncthreads();

    // epilogue: thread t -> atom a = t>>3, h-slice hb = (t&7)*8
    {
        int a  = t >> 3;
        int hb = (t & 7) * 8;
        float p = 0.0f;
#pragma unroll
        for (int j = 0; j < 8; j++) {
            float hv = sacc[a * SA_RS + hb + j] + b1[hb + j];
            p = fmaf(silu_f(hv), W2[hb + j], p);
        }
#pragma unroll
        for (int off = 1; off < 8; off <<= 1)
            p += __shfl_xor_sync(0xffffffffu, p, off);

        if ((t & 7) == 0) {
            int i = base + a;
            if (i < n) {
                float qi = p + b2[0];
                d_qraw[i] = qi;
                int gg = batch[i];
                atomicAdd(&d_gsum[gg * NSLOT + (i & (NSLOT - 1))], qi);
                if (i == 0     || batch[i - 1] != gg) d_gstart[gg] = i;
                if (i == n - 1 || batch[i + 1] != gg) d_gend[gg]   = i + 1;
            }
        }
    }
}

// ---------------------------------------------------------------------------
// K2: pack {pos, centered q} into float4 (R14 verbatim).
// ---------------------------------------------------------------------------
__global__ void pack_kernel(const float* __restrict__ pos,
                            const int* __restrict__ batch, int n, int nb) {
    __shared__ float smean[MAXB];
    int t = threadIdx.x;
    if (t < MAXB) smean[t] = 0.0f;
    __syncthreads();
    for (int s = t; s < nb * NSLOT; s += 256)
        atomicAdd(&smean[s / NSLOT], d_gsum[s]);
    __syncthreads();

    int i = blockIdx.x * 256 + t;
    if (i < n) {
        int g = batch[i];
        float cnt  = (float)max(1, d_gend[g] - d_gstart[g]);
        float mean = smean[g] / cnt;
        float qc = d_qraw[i] - mean;
        d_qpos[i] = make_float4(pos[3 * i], pos[3 * i + 1], pos[3 * i + 2], qc);
    }
}

// ---------------------------------------------------------------------------
// K3: screened Coulomb pair sum (R14 verbatim: clamp-free main + tail).
// ---------------------------------------------------------------------------
__device__ __forceinline__ float pair_term(float4 pj, float4 pi,
                                           float soft2, float nl, float& k_out) {
    float dx = pj.x - pi.x;
    float dy = pj.y - pi.y;
    float dz = pj.z - pi.z;
    float r2 = fmaf(dx, dx, fmaf(dy, dy, fmaf(dz, dz, soft2)));
    float rinv = fast_rsqrt(r2);
    float r = r2 * rinv;
    k_out = fast_ex2(nl * r) * rinv;
    return pj.w;
}

__global__ void pair_kernel(const int* __restrict__ batch,
                            const float* __restrict__ scr_p,
                            const float* __restrict__ soft_p,
                            float* __restrict__ out, int n) {
    if (blockIdx.x == 0) {
#pragma unroll
        for (int s = threadIdx.x; s < MAXB * NSLOT; s += 256)
            d_gsum[s] = 0.0f;
    }

    int i    = (blockIdx.x * blockDim.x + threadIdx.x) >> 5;
    int lane = threadIdx.x & 31;
    if (i >= n) return;

    const float4* __restrict__ qp = d_qpos;

    float scr   = *scr_p;
    float soft  = *soft_p;
    float soft2 = soft * soft;
    const float nl = -scr * LOG2E;

    int g  = batch[i];
    int gs = d_gstart[g];
    int ge = d_gend[g];
    int len   = ge - gs;
    int nfull = len >> 7;

    float4 pi = qp[i];
    float acc = 0.0f;

    const float4* p = qp + gs + lane;
    for (int it = 0; it < nfull; it++) {
        float4 p0 = p[0];
        float4 p1 = p[32];
        float4 p2 = p[64];
        float4 p3 = p[96];
        float k0, k1, k2, k3;
        float q0 = pair_term(p0, pi, soft2, nl, k0);
        float q1 = pair_term(p1, pi, soft2, nl, k1);
        float q2 = pair_term(p2, pi, soft2, nl, k2);
        float q3 = pair_term(p3, pi, soft2, nl, k3);
        acc = fmaf(q0, k0, acc);
        acc = fmaf(q1, k1, acc);
        acc = fmaf(q2, k2, acc);
        acc = fmaf(q3, k3, acc);
        p += 128;
    }
    for (int j = gs + (nfull << 7) + lane; j < ge; j += 32) {
        float4 pj = qp[j];
        float kk;
        float qw = pair_term(pj, pi, soft2, nl, kk);
        acc = fmaf(qw, kk, acc);
    }

    if (lane == 0) {
        float ks;
        float qs = pair_term(pi, pi, soft2, nl, ks);
        acc -= qs * ks;
    }

#pragma unroll
    for (int off = 16; off; off >>= 1)
        acc += __shfl_down_sync(0xffffffffu, acc, off);

    if (lane == 0) out[i] = 0.5f * pi.w * acc;
}

// ---------------------------------------------------------------------------
// launch
// inputs: 0:x 1:pos 2:cell 3:W1 4:b1 5:W2 6:b2 7:screening 8:softening 9:batch
// ---------------------------------------------------------------------------
extern "C" void kernel_launch(void* const* d_in, const int* in_sizes, int n_in,
                              void* d_out, int out_size) {
    const float* x     = (const float*)d_in[0];
    const float* pos   = (const float*)d_in[1];
    const float* W1    = (const float*)d_in[3];
    const float* b1    = (const float*)d_in[4];
    const float* W2    = (const float*)d_in[5];
    const float* b2    = (const float*)d_in[6];
    const float* scr   = (const float*)d_in[7];
    const float* soft  = (const float*)d_in[8];
    const int*   batch = (const int*)d_in[9];
    float* out = (float*)d_out;

    int n  = in_sizes[9];
    int nb = in_sizes[2] / 9;
    if (nb > MAXB) nb = MAXB;

    mlp_kernel<<<(n + 31) / 32, 256>>>(x, W1, b1, W2, b2, batch, n);
    pack_kernel<<<(n + 255) / 256, 256>>>(pos, batch, n, nb);
    int threads = 256;
    int blocks  = (n * 32 + threads - 1) / threads;
    pair_kernel<<<blocks, threads>>>(batch, scr, soft, out, n);
}